// round 7
// baseline (speedup 1.0000x reference)
#include <cuda_runtime.h>
#include <cstdint>
#include <cstddef>

#define Bz 64
#define Sz 2048
#define Hz 256
#define PS 200   // partial row stride (floats), 192 used

typedef unsigned long long ull;

// ---------------- scratch (static device arrays: no runtime allocation) -----
__device__ float g_A0[(size_t)Bz * Sz * Hz];   // x@w_h0 + b_h0, [B,S,H]
__device__ float g_H1[(size_t)Bz * Sz * Hz];   // h1 states,     [B,S,H]
__device__ float g_h0r[2][Bz * Hz];            // h0 state ring  [slot][b*256+k]
__device__ float g_h1r[2][Bz * Hz];            // h1 state ring

// packed fp32x2 FMA (sm_100+)
__device__ __forceinline__ ull ffma2(ull a, ull b, ull c) {
    ull d;
    asm("fma.rn.f32x2 %0, %1, %2, %3;" : "=l"(d) : "l"(a), "l"(b), "l"(c));
    return d;
}
__device__ __forceinline__ ull dupf(float x) {
    ull r;
    asm("mov.b64 %0, {%1, %1};" : "=l"(r) : "f"(x));
    return r;
}
__device__ __forceinline__ float2 asf2(ull u) {
    float2 f;
    asm("mov.b64 {%0, %1}, %2;" : "=f"(f.x), "=f"(f.y) : "l"(u));
    return f;
}
__device__ __forceinline__ uint32_t smem_u32(const void* p) {
    return (uint32_t)__cvta_generic_to_shared(p);
}
__device__ __forceinline__ void mbar_wait_acq(uint32_t mbar, uint32_t parity) {
    asm volatile(
        "{\n\t"
        ".reg .pred P;\n\t"
        "WLP_%=:\n\t"
        "mbarrier.try_wait.parity.acquire.cluster.shared::cta.b64 P, [%0], %1;\n\t"
        "@!P bra WLP_%=;\n\t"
        "}\n\t"
        :: "r"(mbar), "r"(parity) : "memory");
}
__device__ __forceinline__ void mbar_arrive_rel(uint32_t mbar_local, int rank) {
    uint32_t rm;
    asm("mapa.shared::cluster.u32 %0, %1, %2;" : "=r"(rm) : "r"(mbar_local), "r"(rank));
    asm volatile("mbarrier.arrive.release.cluster.shared::cluster.b64 _, [%0];"
                 :: "r"(rm) : "memory");
}

// ---------------- C[M,256] = A[M,256] @ W[256,256] + bias (f32x2 math) ------
__global__ __launch_bounds__(256) void gemm256(const float* __restrict__ A,
                                               const float* __restrict__ W,
                                               const float* __restrict__ bias,
                                               float* __restrict__ C) {
    __shared__ float As[64][68];
    __shared__ float Ws[64][64];
    const int tid = threadIdx.x;
    const int tm = tid >> 4, tn = tid & 15;
    const int m0 = blockIdx.x * 64, n0 = blockIdx.y * 64;

    ull acc[4][2];
#pragma unroll
    for (int i = 0; i < 4; ++i) { acc[i][0] = 0ull; acc[i][1] = 0ull; }
    const float4 bv = *(const float4*)&bias[n0 + tn * 4];

    for (int k0 = 0; k0 < 256; k0 += 64) {
#pragma unroll
        for (int f = 0; f < 4; ++f) {
            int v  = tid + f * 256;
            int r0 = v >> 4;
            int c4 = (v & 15) << 2;
            *(float4*)&As[r0][c4] = *(const float4*)&A[(size_t)(m0 + r0) * 256 + k0 + c4];
            *(float4*)&Ws[r0][c4] = *(const float4*)&W[(size_t)(k0 + r0) * 256 + n0 + c4];
        }
        __syncthreads();
#pragma unroll 8
        for (int kk = 0; kk < 64; ++kk) {
            ulonglong2 wv = *(const ulonglong2*)&Ws[kk][tn * 4];
#pragma unroll
            for (int i = 0; i < 4; ++i) {
                ull d = dupf(As[tm * 4 + i][kk]);
                acc[i][0] = ffma2(d, wv.x, acc[i][0]);
                acc[i][1] = ffma2(d, wv.y, acc[i][1]);
            }
        }
        __syncthreads();
    }
#pragma unroll
    for (int i = 0; i < 4; ++i) {
        float2 lo = asf2(acc[i][0]), hi = asf2(acc[i][1]);
        float4 o = make_float4(lo.x + bv.x, lo.y + bv.y, hi.x + bv.z, hi.y + bv.w);
        *(float4*)&C[(size_t)(m0 + tm * 4 + i) * 256 + n0 + tn * 4] = o;
    }
}

// ---------------- persistent clustered recurrence (two-group pipeline) ------
// 32 clusters x 4 CTAs x 512 threads. Cluster owns batch rows {2c, 2c+1} as
// groups g=0,1; CTA rank r owns columns [64r,64r+64) (weights in REGISTERS).
// Each interval t runs two half-phases (one per group). A half does:
//   FMA(g) -> partials -> sync -> reduce+epilogue(publish L2 ring) ->
//   stage OTHER group's in-flight LDG data into smem -> sync ->
//   arrive mbar[g] -> wait mbar[g] (the only rendezvous) ->
//   issue LDGs for g's NEXT step (hidden under the other group's FMA).
// Per-matrix pipeline (per group): G0 h0n[t]; G1 a1[t-1] local; G2 h1n[t-2].

__global__ void __cluster_dims__(4, 1, 1) __launch_bounds__(512, 1)
rnn_k(const float* __restrict__ u_h0, const float* __restrict__ w_h1,
      const float* __restrict__ u_h1, const float* __restrict__ b_h1,
      float* __restrict__ hf) {
    __shared__ float hs[2][1024];       // per-group staged: [k][h0,h0,h1,h1]
    __shared__ float ps[16 * PS];       // k-split partials (shared by halves)
    __shared__ float a1s[2][128];       // per-group a1 ring [g][parity*64+j]
    __shared__ ull   mbar[2];           // per-group rendezvous barriers

    const int tid = threadIdx.x;
    const int ks  = tid >> 5;                 // warp id = k-split (16)
    const int jg  = tid & 31;                 // lane = j-pair
    const int bg  = (blockIdx.x >> 2) * 2;    // first batch row of cluster
    const int j0  = (blockIdx.x & 3) * 64;    // first col of this CTA

    // ---- persistent weights in registers ----
    ull wr0[16], wr1[16], wr2[16];
#pragma unroll
    for (int kk = 0; kk < 16; ++kk) {
        size_t o = (size_t)(ks * 16 + kk) * 256 + j0 + jg * 2;
        wr0[kk] = __ldg((const ull*)&u_h0[o]);
        wr1[kk] = __ldg((const ull*)&w_h1[o]);
        wr2[kk] = __ldg((const ull*)&u_h1[o]);
    }

    // zero staged buffers (states at t=0 are 0)
    for (int i = tid; i < 2048; i += 512) ((float*)hs)[i] = 0.f;

    const uint32_t mb0 = smem_u32(&mbar[0]);
    const uint32_t mb1 = smem_u32(&mbar[1]);
    if (tid == 0) {
        asm volatile("mbarrier.init.shared.b64 [%0], %1;" :: "r"(mb0), "r"(4) : "memory");
        asm volatile("mbarrier.init.shared.b64 [%0], %1;" :: "r"(mb1), "r"(4) : "memory");
    }
    __syncthreads();
    asm volatile("barrier.cluster.arrive.aligned;" ::: "memory");
    asm volatile("barrier.cluster.wait.aligned;" ::: "memory");

    // epilogue identity (threads [0,192)): em 0..2, ej 0..63
    const int eo = tid;
    const int em = eo >> 6;
    const int ej = eo & 63;
    const bool epi = (eo < 192);
    const float bias = b_h1[j0 + ej];

    // stage identity: sw = which state (0:h0,1:h1), sk = k
    const int sw = tid >> 8, sk = tid & 255;

    float stg[2];                             // in-flight staged state values
    float a0pre[2];                           // prefetched A0 for current step
    stg[0] = stg[1] = 0.f;
#pragma unroll
    for (int g = 0; g < 2; ++g)
        a0pre[g] = (em == 0 && epi)
                 ? __ldcg(&g_A0[(size_t)(bg + g) * Sz * 256 + j0 + ej]) : 0.f;

    for (int t = 0; t < Sz + 2; ++t) {
#pragma unroll
        for (int g = 0; g < 2; ++g) {
            // ---- FMA over staged states of group g ----
            ull a0 = 0, a1m = 0, a2 = 0;
            {
                const float* hp = &hs[g][ks * 64];
#pragma unroll
                for (int kk = 0; kk < 16; ++kk) {
                    ulonglong2 hq = *(const ulonglong2*)(hp + kk * 4);
                    a0  = ffma2(hq.x, wr0[kk], a0);
                    a1m = ffma2(hq.x, wr1[kk], a1m);
                    a2  = ffma2(hq.y, wr2[kk], a2);
                }
            }
            {
                float* pb = ps + ks * PS + jg * 2;
                *(ull*)&pb[0]   = a0;
                *(ull*)&pb[64]  = a1m;
                *(ull*)&pb[128] = a2;
            }
            __syncthreads();

            // ---- reduce + epilogue (publish via L2 rings) ----
            if (epi) {
                float s = 0.f;
#pragma unroll
                for (int p = 0; p < 16; ++p) s += ps[p * PS + eo];

                const int row  = bg + g;
                const int gofs = row * 256 + j0 + ej;
                if (em == 0) {
                    if (t < Sz) {
                        float v = tanhf(s + a0pre[g]);
                        g_h0r[t & 1][gofs] = v;
                        if (t == Sz - 1) hf[(row * 2 + 0) * 256 + j0 + ej] = v;
                    }
                } else if (em == 1) {
                    if (t >= 1 && t <= Sz)
                        a1s[g][((t - 1) & 1) * 64 + ej] = s + bias;  // a1[t-1]
                } else {
                    if (t >= 2) {
                        float v = tanhf(s + a1s[g][(t & 1) * 64 + ej]); // +a1[t-2]
                        if (t <= Sz) g_h1r[t & 1][gofs] = v;
                        g_H1[((size_t)row * Sz + (t - 2)) * 256 + j0 + ej] = v;
                        if (t == Sz + 1) hf[(row * 2 + 1) * 256 + j0 + ej] = v;
                    }
                }
            }

            // ---- stage OTHER group's in-flight LDG data into its smem buf ----
            if (!(t == 0 && g == 0))
                *(ull*)&hs[1 - g][sk * 4 + 2 * sw] = dupf(stg[1 - g]);
            __syncthreads();    // epilogue STGs + staging visible CTA-wide

            // ---- rendezvous for group g ----
            if (t <= Sz) {
                if (tid < 4) mbar_arrive_rel((g ? mb1 : mb0), tid);
                mbar_wait_acq((g ? mb1 : mb0), t & 1);

                // ---- issue LDGs for group g's step t+1 (consumed next half) ----
                if (sw == 0) {
                    stg[g] = __ldcg(&g_h0r[t & 1][(bg + g) * 256 + sk]); // h0n[t]
                } else {
                    stg[g] = (t >= 2)
                           ? __ldcg(&g_h1r[t & 1][(bg + g) * 256 + sk]) // h1n[t-2]
                           : 0.f;
                }
                if (em == 0 && epi)
                    a0pre[g] = (t + 1 < Sz)
                             ? __ldcg(&g_A0[((size_t)(bg + g) * Sz + t + 1) * 256 + j0 + ej])
                             : 0.f;
            }
        }
    }

    // straggler guard: remote arrives must land before any CTA exits
    asm volatile("barrier.cluster.arrive.aligned;" ::: "memory");
    asm volatile("barrier.cluster.wait.aligned;" ::: "memory");
}

// ---------------- launch ----------------------------------------------------
extern "C" void kernel_launch(void* const* d_in, const int* in_sizes, int n_in,
                              void* d_out, int out_size) {
    const float* x    = (const float*)d_in[0];
    const float* w_h0 = (const float*)d_in[1];
    const float* u_h0 = (const float*)d_in[2];
    const float* b_h0 = (const float*)d_in[3];
    const float* w_h1 = (const float*)d_in[4];
    const float* u_h1 = (const float*)d_in[5];
    const float* b_h1 = (const float*)d_in[6];
    const float* w_q  = (const float*)d_in[7];
    const float* b_q  = (const float*)d_in[8];

    float* out = (float*)d_out;                       // [B,S,O]
    float* hf  = out + (size_t)Bz * Sz * Hz;          // [B,2,H]

    float *pA0 = nullptr, *pH1 = nullptr;
    cudaGetSymbolAddress((void**)&pA0, g_A0);
    cudaGetSymbolAddress((void**)&pH1, g_H1);

    gemm256<<<dim3((Bz * Sz) / 64, 4), 256>>>(x, w_h0, b_h0, pA0);
    rnn_k<<<128, 512>>>(u_h0, w_h1, u_h1, b_h1, hf);
    gemm256<<<dim3((Bz * Sz) / 64, 4), 256>>>(pH1, w_q, b_q, out);
}